// round 5
// baseline (speedup 1.0000x reference)
#include <cuda_runtime.h>
#include <cstdint>
#include <cmath>

#define TQ   4096
#define DM   1024
#define NH   16
#define DH   64

// Scratch (__device__ globals: allocation-free rule)
__device__ float g_qkv[(size_t)TQ * 3 * DM];     // [t][3c]; Q,K col-permuted+scaled; V normal
__device__ float g_vT[(size_t)DM * TQ];          // V transposed [c][t], t-permuted
__device__ float g_att[(size_t)TQ * DM];         // attn out, already proj-A layout
__device__ float g_xr[(size_t)TQ * DM];          // x rounded + k-permuted
__device__ float g_wqkvT[(size_t)3 * DM * DM];   // [3DM][DM] transposed+permuted
__device__ float g_wprojT[(size_t)DM * DM];      // [DM][DM]  transposed+permuted

// ---------------------------------------------------------------------------
// helpers
// ---------------------------------------------------------------------------
__device__ __forceinline__ unsigned f2tf(float x) {
    unsigned u;
    asm("cvt.rna.tf32.f32 %0, %1;" : "=r"(u) : "f"(x));
    return u;
}
__device__ __forceinline__ float f2tff(float x) { return __uint_as_float(f2tf(x)); }

__device__ __forceinline__ void mma_tf32(float* d, const unsigned* a,
                                         unsigned b0, unsigned b1) {
    asm volatile(
        "mma.sync.aligned.m16n8k8.row.col.f32.tf32.tf32.f32 "
        "{%0,%1,%2,%3}, {%4,%5,%6,%7}, {%8,%9}, {%0,%1,%2,%3};\n"
        : "+f"(d[0]), "+f"(d[1]), "+f"(d[2]), "+f"(d[3])
        : "r"(a[0]), "r"(a[1]), "r"(a[2]), "r"(a[3]), "r"(b0), "r"(b1));
}

__device__ __forceinline__ uint32_t s2u(const void* p) {
    uint32_t a;
    asm("{ .reg .u64 t; cvta.to.shared.u64 t, %1; cvt.u32.u64 %0, t; }"
        : "=r"(a) : "l"(p));
    return a;
}
__device__ __forceinline__ void cpa16(uint32_t dst, const void* src) {
    asm volatile("cp.async.cg.shared.global [%0], [%1], 16;\n" :: "r"(dst), "l"(src));
}
__device__ __forceinline__ void cpa_commit() {
    asm volatile("cp.async.commit_group;\n");
}
template <int N> __device__ __forceinline__ void cpa_wait() {
    asm volatile("cp.async.wait_group %0;\n" :: "n"(N));
}

// 8-group permutation: logical l goes to physical 2*(l&3) + ((l&7)>>2)
// (inverse: physical p holds logical (p&1)*4 + (p>>1))
__device__ __forceinline__ int pin8(int i) { return 2 * (i & 3) + ((i & 7) >> 2); }

// ---------------------------------------------------------------------------
// pre-processing
// ---------------------------------------------------------------------------
__global__ void cvt_perm_k(const float* __restrict__ in, float* __restrict__ out,
                           int n)
{
    int q = blockIdx.x * blockDim.x + threadIdx.x;
    if (q * 4 >= n) return;
    int gp    = q * 4;
    int group = gp & ~7;
    int off   = gp & 7;
    float4 v;
    if (off == 0)
        v = make_float4(in[group + 0], in[group + 4], in[group + 1], in[group + 5]);
    else
        v = make_float4(in[group + 2], in[group + 6], in[group + 3], in[group + 7]);
    v.x = f2tff(v.x); v.y = f2tff(v.y); v.z = f2tff(v.z); v.w = f2tff(v.w);
    *(float4*)(out + gp) = v;
}

// in [R][C] (row stride ldin) -> out [C][R] with output inner dim (R) permuted
// in 8-groups, rounded. block (32,8), grid (C/32, R/32).
__global__ void trans_perm(const float* __restrict__ in, float* __restrict__ out,
                           int R, int C, int ldin)
{
    __shared__ float t[32][33];
    int c0 = blockIdx.x * 32, r0 = blockIdx.y * 32;
    int tx = threadIdx.x, ty = threadIdx.y;
#pragma unroll
    for (int i = 0; i < 4; i++)
        t[ty + 8 * i][tx] = in[(size_t)(r0 + ty + 8 * i) * ldin + c0 + tx];
    __syncthreads();
    int p   = tx & 7;
    int txl = (tx & ~7) | (((tx & 1) << 2) + (p >> 1));   // logical src for phys tx
#pragma unroll
    for (int i = 0; i < 4; i++)
        out[(size_t)(c0 + ty + 8 * i) * R + r0 + tx] = f2tff(t[txl][ty + 8 * i]);
}

// ---------------------------------------------------------------------------
// tf32 GEMM on k-permuted operands: C[M,N] = A[M,K] @ B[N,K]^T
// BM=128, BN=128, BK=32, 256 thr, 2-stage cp.async, LDS.64 fragments.
// MODE 1 (qkv): round; Q cols (<DM) scaled 0.125; Q,K cols stored permuted.
// ---------------------------------------------------------------------------
#define GST 40
#define GSTAGE (2 * 128 * GST)

template <int MODE>
__global__ __launch_bounds__(256, 2)
void gemm_tf32p(const float* __restrict__ A, const float* __restrict__ B,
                float* __restrict__ C, int M, int N, int K)
{
    __shared__ float sm[2 * GSTAGE];
    const uint32_t s0 = s2u(sm);

    const int tid  = threadIdx.x;
    const int lane = tid & 31;
    const int warp = tid >> 5;
    const int wm   = warp & 3;
    const int wn   = warp >> 2;
    const int bx   = blockIdx.x;
    const int by   = blockIdx.y;
    const int g    = lane >> 2;
    const int tc   = lane & 3;

    const float* Ab = A + (size_t)(by * 128) * K;
    const float* Bb = B + (size_t)(bx * 128) * K;

    float acc[2][8][4];
#pragma unroll
    for (int mt = 0; mt < 2; mt++)
#pragma unroll
        for (int nt = 0; nt < 8; nt++)
#pragma unroll
            for (int j = 0; j < 4; j++) acc[mt][nt][j] = 0.f;

    auto load_stage = [&](int s, int buf) {
        uint32_t dA = s0 + (uint32_t)(buf * GSTAGE) * 4;
        uint32_t dB = dA + (uint32_t)(128 * GST) * 4;
#pragma unroll
        for (int j = 0; j < 4; j++) {
            int idx = tid + j * 256;
            int r = idx >> 3, c4 = (idx & 7) * 4;
            cpa16(dA + (uint32_t)(r * GST + c4) * 4, Ab + (size_t)r * K + s * 32 + c4);
            cpa16(dB + (uint32_t)(r * GST + c4) * 4, Bb + (size_t)r * K + s * 32 + c4);
        }
        cpa_commit();
    };

    load_stage(0, 0);
    load_stage(1, 1);

    const int S = K / 32;
    for (int s = 0; s < S; s++) {
        if (s + 1 < S) cpa_wait<1>(); else cpa_wait<0>();
        __syncthreads();

        const float* As = sm + (s & 1) * GSTAGE;
        const float* Bs = As + 128 * GST;

#pragma unroll
        for (int ks = 0; ks < 4; ks++) {
            int kc = ks * 8 + 2 * tc;
            unsigned a[2][4];
#pragma unroll
            for (int mt = 0; mt < 2; mt++) {
                int row = wm * 32 + mt * 16 + g;
                float2 lo = *(const float2*)(As + row * GST + kc);
                float2 hi = *(const float2*)(As + (row + 8) * GST + kc);
                a[mt][0] = __float_as_uint(lo.x);
                a[mt][1] = __float_as_uint(hi.x);
                a[mt][2] = __float_as_uint(lo.y);
                a[mt][3] = __float_as_uint(hi.y);
            }
#pragma unroll
            for (int nt = 0; nt < 8; nt++) {
                int nr = wn * 64 + nt * 8 + g;
                float2 b = *(const float2*)(Bs + nr * GST + kc);
                mma_tf32(acc[0][nt], a[0], __float_as_uint(b.x), __float_as_uint(b.y));
                mma_tf32(acc[1][nt], a[1], __float_as_uint(b.x), __float_as_uint(b.y));
            }
        }
        __syncthreads();
        if (s + 2 < S) load_stage(s + 2, s & 1);
    }

    const int pin0 = pin8(2 * tc);
    const int pin1 = pin8(2 * tc + 1);

#pragma unroll
    for (int mt = 0; mt < 2; mt++)
#pragma unroll
        for (int nt = 0; nt < 8; nt++) {
            int r0 = by * 128 + wm * 32 + mt * 16 + g;
            int c0 = bx * 128 + wn * 64 + nt * 8 + 2 * tc;
            float v0 = acc[mt][nt][0], v1 = acc[mt][nt][1];
            float v2 = acc[mt][nt][2], v3 = acc[mt][nt][3];
            if (MODE == 1) {
                float sc = (c0 < DM) ? 0.125f : 1.0f;
                v0 = f2tff(v0 * sc); v1 = f2tff(v1 * sc);
                v2 = f2tff(v2 * sc); v3 = f2tff(v3 * sc);
                if (c0 < 2 * DM) {                 // Q,K: permuted scalar stores
                    int cb = c0 & ~7;
                    C[(size_t)r0 * N + cb + pin0]       = v0;
                    C[(size_t)r0 * N + cb + pin1]       = v1;
                    C[(size_t)(r0 + 8) * N + cb + pin0] = v2;
                    C[(size_t)(r0 + 8) * N + cb + pin1] = v3;
                } else {                           // V: normal layout
                    *(float2*)(C + (size_t)r0 * N + c0)       = make_float2(v0, v1);
                    *(float2*)(C + (size_t)(r0 + 8) * N + c0) = make_float2(v2, v3);
                }
            } else {
                *(float2*)(C + (size_t)r0 * N + c0)       = make_float2(v0, v1);
                *(float2*)(C + (size_t)(r0 + 8) * N + c0) = make_float2(v2, v3);
            }
        }
}

// ---------------------------------------------------------------------------
// Causal flash attention: 64 q-rows, 4 warps, 3 CTA/SM. All fragment loads
// LDS.64 (Q/K head-dim permuted in gmem; P cols + V^T t-dim permuted).
// ---------------------------------------------------------------------------
#define ROWP 68
__global__ __launch_bounds__(128) void attn_fwd()
{
    extern __shared__ float sm[];
    float* Qs = sm;                    // [64 q][ROWP]  (head-dim permuted)
    float* Ks = Qs + 64 * ROWP;        // [64 kv][ROWP] (head-dim permuted)
    float* Vs = Ks + 64 * ROWP;        // [64 d][ROWP]  (kv permuted within 8)
    float* Ps = Vs + 64 * ROWP;        // [64 q][ROWP]  (kv permuted within 8)
    const uint32_t sb = s2u(sm);

    const int tid  = threadIdx.x;
    const int lane = tid & 31;
    const int warp = tid >> 5;
    const int h    = blockIdx.y;
    const int qt   = (int)gridDim.x - 1 - (int)blockIdx.x;
    const int q0   = qt * 64;
    const int g    = lane >> 2;
    const int tc   = lane & 3;
    const int pin0 = pin8(2 * tc);
    const int pin1 = pin8(2 * tc + 1);

    // ---- prologue: Q tile ----
#pragma unroll
    for (int i = 0; i < 8; i++) {
        int idx = tid + i * 128;
        int r   = idx >> 4;
        int c4  = (idx & 15) * 4;
        cpa16(sb + (uint32_t)(r * ROWP + c4) * 4,
              g_qkv + (size_t)(q0 + r) * (3 * DM) + h * DH + c4);
    }
    cpa_commit();

    float o[8][4];
#pragma unroll
    for (int nt = 0; nt < 8; nt++)
#pragma unroll
        for (int j = 0; j < 4; j++) o[nt][j] = 0.f;
    float mA = -INFINITY, mB = -INFINITY, lA = 0.f, lB = 0.f;

    for (int t = 0; t <= qt; t++) {
        __syncthreads();
#pragma unroll
        for (int i = 0; i < 8; i++) {              // K tile [kv][d]
            int idx = tid + i * 128;
            int r   = idx >> 4;
            int c4  = (idx & 15) * 4;
            cpa16(sb + (uint32_t)(64 * ROWP + r * ROWP + c4) * 4,
                  g_qkv + (size_t)(t * 64 + r) * (3 * DM) + DM + h * DH + c4);
        }
#pragma unroll
        for (int i = 0; i < 8; i++) {              // V^T tile [d][kv]
            int idx = tid + i * 128;
            int r   = idx >> 4;
            int c4  = (idx & 15) * 4;
            cpa16(sb + (uint32_t)(128 * ROWP + r * ROWP + c4) * 4,
                  g_vT + (size_t)(h * DH + r) * TQ + t * 64 + c4);
        }
        cpa_commit();
        cpa_wait<0>();
        __syncthreads();

        // ---- S = Q @ K^T ----
        float s[8][4];
#pragma unroll
        for (int nt = 0; nt < 8; nt++)
#pragma unroll
            for (int j = 0; j < 4; j++) s[nt][j] = 0.f;

#pragma unroll
        for (int ks = 0; ks < 8; ks++) {
            int kc = ks * 8 + 2 * tc;
            int row = warp * 16 + g;
            float2 lo = *(const float2*)(Qs + row * ROWP + kc);
            float2 hi = *(const float2*)(Qs + (row + 8) * ROWP + kc);
            unsigned a[4] = { __float_as_uint(lo.x), __float_as_uint(hi.x),
                              __float_as_uint(lo.y), __float_as_uint(hi.y) };
#pragma unroll
            for (int nt = 0; nt < 8; nt++) {
                float2 b = *(const float2*)(Ks + (nt * 8 + g) * ROWP + kc);
                mma_tf32(s[nt], a, __float_as_uint(b.x), __float_as_uint(b.y));
            }
        }

        // ---- causal mask on diagonal tile ----
        if (t == qt) {
            int qlA = warp * 16 + g;
            int qlB = qlA + 8;
#pragma unroll
            for (int nt = 0; nt < 8; nt++) {
                int k0 = nt * 8 + 2 * tc;
                if (k0     > qlA) s[nt][0] = -INFINITY;
                if (k0 + 1 > qlA) s[nt][1] = -INFINITY;
                if (k0     > qlB) s[nt][2] = -INFINITY;
                if (k0 + 1 > qlB) s[nt][3] = -INFINITY;
            }
        }

        // ---- online softmax ----
        float rA = -INFINITY, rB = -INFINITY;
#pragma unroll
        for (int nt = 0; nt < 8; nt++) {
            rA = fmaxf(rA, fmaxf(s[nt][0], s[nt][1]));
            rB = fmaxf(rB, fmaxf(s[nt][2], s[nt][3]));
        }
        rA = fmaxf(rA, __shfl_xor_sync(0xffffffffu, rA, 1));
        rA = fmaxf(rA, __shfl_xor_sync(0xffffffffu, rA, 2));
        rB = fmaxf(rB, __shfl_xor_sync(0xffffffffu, rB, 1));
        rB = fmaxf(rB, __shfl_xor_sync(0xffffffffu, rB, 2));

        float mAn = fmaxf(mA, rA), mBn = fmaxf(mB, rB);
        float fA = __expf(mA - mAn), fB = __expf(mB - mBn);

        float sumA = 0.f, sumB = 0.f;
        int rowL = warp * 16 + g;
#pragma unroll
        for (int nt = 0; nt < 8; nt++) {
            float p0 = f2tff(__expf(s[nt][0] - mAn));
            float p1 = f2tff(__expf(s[nt][1] - mAn));
            float p2 = f2tff(__expf(s[nt][2] - mBn));
            float p3 = f2tff(__expf(s[nt][3] - mBn));
            sumA += p0 + p1;
            sumB += p2 + p3;
            int cb = nt * 8;
            Ps[rowL * ROWP + cb + pin0]       = p0;
            Ps[rowL * ROWP + cb + pin1]       = p1;
            Ps[(rowL + 8) * ROWP + cb + pin0] = p2;
            Ps[(rowL + 8) * ROWP + cb + pin1] = p3;
        }
        sumA += __shfl_xor_sync(0xffffffffu, sumA, 1);
        sumA += __shfl_xor_sync(0xffffffffu, sumA, 2);
        sumB += __shfl_xor_sync(0xffffffffu, sumB, 1);
        sumB += __shfl_xor_sync(0xffffffffu, sumB, 2);

        lA = lA * fA + sumA;
        lB = lB * fB + sumB;
        mA = mAn; mB = mBn;
#pragma unroll
        for (int nt = 0; nt < 8; nt++) {
            o[nt][0] *= fA; o[nt][1] *= fA;
            o[nt][2] *= fB; o[nt][3] *= fB;
        }
        __syncwarp();

        // ---- O += P @ V  (V^T layout: rows = d, cols = kv-permuted) ----
#pragma unroll
        for (int ks = 0; ks < 8; ks++) {
            int kc = ks * 8 + 2 * tc;
            int row = warp * 16 + g;
            float2 lo = *(const float2*)(Ps + row * ROWP + kc);
            float2 hi = *(const float2*)(Ps + (row + 8) * ROWP + kc);
            unsigned a[4] = { __float_as_uint(lo.x), __float_as_uint(hi.x),
                              __float_as_uint(lo.y), __float_as_uint(hi.y) };
#pragma unroll
            for (int nt = 0; nt < 8; nt++) {
                float2 b = *(const float2*)(Vs + (nt * 8 + g) * ROWP + kc);
                mma_tf32(o[nt], a, __float_as_uint(b.x), __float_as_uint(b.y));
            }
        }
    }

    // ---- epilogue: normalize, round, store in proj-A (k-permuted) layout ----
    float invA = 1.f / lA, invB = 1.f / lB;
    int rowA = q0 + warp * 16 + g;
#pragma unroll
    for (int nt = 0; nt < 8; nt++) {
        int cb = h * DH + nt * 8;
        g_att[(size_t)rowA * DM + cb + pin0]       = f2tff(o[nt][0] * invA);
        g_att[(size_t)rowA * DM + cb + pin1]       = f2tff(o[nt][1] * invA);
        g_att[(size_t)(rowA + 8) * DM + cb + pin0] = f2tff(o[nt][2] * invB);
        g_att[(size_t)(rowA + 8) * DM + cb + pin1] = f2tff(o[nt][3] * invB);
    }
}

// ---------------------------------------------------------------------------
// Launch
// ---------------------------------------------------------------------------
extern "C" void kernel_launch(void* const* d_in, const int* in_sizes, int n_in,
                              void* d_out, int out_size)
{
    const float* x      = (const float*)d_in[0];
    const float* w_qkv  = (const float*)d_in[1];
    const float* w_proj = (const float*)d_in[2];
    float* out          = (float*)d_out;

    float *qkv_p, *vT_p, *att_p, *xr_p, *wqkvT_p, *wprojT_p;
    cudaGetSymbolAddress((void**)&qkv_p,    g_qkv);
    cudaGetSymbolAddress((void**)&vT_p,     g_vT);
    cudaGetSymbolAddress((void**)&att_p,    g_att);
    cudaGetSymbolAddress((void**)&xr_p,     g_xr);
    cudaGetSymbolAddress((void**)&wqkvT_p,  g_wqkvT);
    cudaGetSymbolAddress((void**)&wprojT_p, g_wprojT);

    const int attn_smem = 4 * 64 * ROWP * (int)sizeof(float);   // 69632 -> 3 CTA/SM
    cudaFuncSetAttribute(attn_fwd, cudaFuncAttributeMaxDynamicSharedMemorySize,
                         attn_smem);

    // 0) pre-process
    cvt_perm_k<<<(TQ * DM / 4 + 255) / 256, 256>>>(x, xr_p, TQ * DM);
    trans_perm<<<dim3(3 * DM / 32, DM / 32), dim3(32, 8)>>>(w_qkv, wqkvT_p,
                                                            DM, 3 * DM, 3 * DM);
    trans_perm<<<dim3(DM / 32, DM / 32), dim3(32, 8)>>>(w_proj, wprojT_p,
                                                        DM, DM, DM);

    // 1) QKV projection (rounds; scales+permutes Q, permutes K; V normal)
    gemm_tf32p<1><<<dim3(3 * DM / 128, TQ / 128), 256>>>(
        xr_p, wqkvT_p, qkv_p, TQ, 3 * DM, DM);

    // 1b) V -> V^T [c][t] with t permuted in 8-groups
    trans_perm<<<dim3(DM / 32, TQ / 32), dim3(32, 8)>>>(qkv_p + 2 * DM, vT_p,
                                                        TQ, DM, 3 * DM);

    // 2) causal attention (epilogue emits proj-A layout)
    attn_fwd<<<dim3(TQ / 64, NH), 128, attn_smem>>>();

    // 3) output projection
    gemm_tf32p<0><<<dim3(DM / 128, TQ / 128), 256>>>(
        att_p, wprojT_p, out, TQ, DM, DM);
}

// round 6
// speedup vs baseline: 1.1005x; 1.1005x over previous
#include <cuda_runtime.h>
#include <cstdint>
#include <cmath>

#define TQ   4096
#define DM   1024
#define NH   16
#define DH   64

// Scratch (__device__ globals: allocation-free rule)
__device__ float g_qkv[(size_t)TQ * 3 * DM];     // [t][3c] rounded, Q pre-scaled
__device__ float g_att[(size_t)TQ * DM];         // attention out (normal layout)
__device__ float g_xr[(size_t)TQ * DM];          // k-permuted rounded A operand
__device__ float g_wqkvT[(size_t)3 * DM * DM];   // [3DM][DM] transposed+permuted
__device__ float g_wprojT[(size_t)DM * DM];      // [DM][DM]  transposed+permuted

// ---------------------------------------------------------------------------
// helpers
// ---------------------------------------------------------------------------
__device__ __forceinline__ unsigned f2tf(float x) {
    unsigned u;
    asm("cvt.rna.tf32.f32 %0, %1;" : "=r"(u) : "f"(x));
    return u;
}
__device__ __forceinline__ float f2tff(float x) { return __uint_as_float(f2tf(x)); }

__device__ __forceinline__ void mma_tf32(float* d, const unsigned* a,
                                         unsigned b0, unsigned b1) {
    asm volatile(
        "mma.sync.aligned.m16n8k8.row.col.f32.tf32.tf32.f32 "
        "{%0,%1,%2,%3}, {%4,%5,%6,%7}, {%8,%9}, {%0,%1,%2,%3};\n"
        : "+f"(d[0]), "+f"(d[1]), "+f"(d[2]), "+f"(d[3])
        : "r"(a[0]), "r"(a[1]), "r"(a[2]), "r"(a[3]), "r"(b0), "r"(b1));
}

__device__ __forceinline__ uint32_t s2u(const void* p) {
    uint32_t a;
    asm("{ .reg .u64 t; cvta.to.shared.u64 t, %1; cvt.u32.u64 %0, t; }"
        : "=r"(a) : "l"(p));
    return a;
}
__device__ __forceinline__ void cpa16(uint32_t dst, const void* src) {
    asm volatile("cp.async.cg.shared.global [%0], [%1], 16;\n" :: "r"(dst), "l"(src));
}
__device__ __forceinline__ void cpa_commit() {
    asm volatile("cp.async.commit_group;\n");
}
template <int N> __device__ __forceinline__ void cpa_wait() {
    asm volatile("cp.async.wait_group %0;\n" :: "n"(N));
}

// ---------------------------------------------------------------------------
// pre-processing
// k-group permutation: physical p in an 8-group holds logical (p>>1)+((p&1)<<2)
// so a thread's logical (tc, tc+4) pair sits at physical (2tc, 2tc+1) -> LDS.64
// ---------------------------------------------------------------------------
__global__ void cvt_perm_k(const float* __restrict__ in, float* __restrict__ out,
                           int n)
{
    int q = blockIdx.x * blockDim.x + threadIdx.x;
    if (q * 4 >= n) return;
    int gp    = q * 4;
    int group = gp & ~7;
    int off   = gp & 7;
    float4 v;
    if (off == 0)
        v = make_float4(in[group + 0], in[group + 4], in[group + 1], in[group + 5]);
    else
        v = make_float4(in[group + 2], in[group + 6], in[group + 3], in[group + 7]);
    v.x = f2tff(v.x); v.y = f2tff(v.y); v.z = f2tff(v.z); v.w = f2tff(v.w);
    *(float4*)(out + gp) = v;
}

// in [R][C] -> out [C][R] with inner (k=R) dim permuted in 8-groups, rounded.
__global__ void wtrans_perm(const float* __restrict__ in,
                            float* __restrict__ out, int R, int C)
{
    __shared__ float t[32][33];
    int c0 = blockIdx.x * 32, r0 = blockIdx.y * 32;
    int tx = threadIdx.x, ty = threadIdx.y;
#pragma unroll
    for (int i = 0; i < 4; i++)
        t[ty + 8 * i][tx] = in[(size_t)(r0 + ty + 8 * i) * C + c0 + tx];
    __syncthreads();
    int p   = tx & 7;
    int txl = (tx & ~7) | ((p >> 1) + ((p & 1) << 2));
#pragma unroll
    for (int i = 0; i < 4; i++)
        out[(size_t)(c0 + ty + 8 * i) * R + r0 + tx] = f2tff(t[txl][ty + 8 * i]);
}

// ---------------------------------------------------------------------------
// tf32 GEMM on k-permuted operands: C[M,N] = A[M,K] @ B[N,K]^T
// BM=128, BN=128, BK=32, 256 thr (warps 4xM x 2xN, warp tile 32x64),
// 2-stage cp.async double buffer, all fragment loads LDS.64.
// MODE 1: round output; scale cols < DM by 0.125 (Q block).
// ---------------------------------------------------------------------------
#define GST 40
#define GSTAGE (2 * 128 * GST)

template <int MODE>
__global__ __launch_bounds__(256, 2)
void gemm_tf32p(const float* __restrict__ A, const float* __restrict__ B,
                float* __restrict__ C, int M, int N, int K)
{
    __shared__ float sm[2 * GSTAGE];
    const uint32_t s0 = s2u(sm);

    const int tid  = threadIdx.x;
    const int lane = tid & 31;
    const int warp = tid >> 5;
    const int wm   = warp & 3;
    const int wn   = warp >> 2;
    const int bx   = blockIdx.x;
    const int by   = blockIdx.y;
    const int g    = lane >> 2;
    const int tc   = lane & 3;

    const float* Ab = A + (size_t)(by * 128) * K;
    const float* Bb = B + (size_t)(bx * 128) * K;

    float acc[2][8][4];
#pragma unroll
    for (int mt = 0; mt < 2; mt++)
#pragma unroll
        for (int nt = 0; nt < 8; nt++)
#pragma unroll
            for (int j = 0; j < 4; j++) acc[mt][nt][j] = 0.f;

    auto load_stage = [&](int s, int buf) {
        uint32_t dA = s0 + (uint32_t)(buf * GSTAGE) * 4;
        uint32_t dB = dA + (uint32_t)(128 * GST) * 4;
#pragma unroll
        for (int j = 0; j < 4; j++) {
            int idx = tid + j * 256;
            int r = idx >> 3, c4 = (idx & 7) * 4;
            cpa16(dA + (uint32_t)(r * GST + c4) * 4, Ab + (size_t)r * K + s * 32 + c4);
            cpa16(dB + (uint32_t)(r * GST + c4) * 4, Bb + (size_t)r * K + s * 32 + c4);
        }
        cpa_commit();
    };

    load_stage(0, 0);
    load_stage(1, 1);

    const int S = K / 32;
    for (int s = 0; s < S; s++) {
        if (s + 1 < S) cpa_wait<1>(); else cpa_wait<0>();
        __syncthreads();

        const float* As = sm + (s & 1) * GSTAGE;
        const float* Bs = As + 128 * GST;

#pragma unroll
        for (int ks = 0; ks < 4; ks++) {
            int kc = ks * 8 + 2 * tc;
            unsigned a[2][4];
#pragma unroll
            for (int mt = 0; mt < 2; mt++) {
                int row = wm * 32 + mt * 16 + g;
                float2 lo = *(const float2*)(As + row * GST + kc);
                float2 hi = *(const float2*)(As + (row + 8) * GST + kc);
                a[mt][0] = __float_as_uint(lo.x);
                a[mt][1] = __float_as_uint(hi.x);
                a[mt][2] = __float_as_uint(lo.y);
                a[mt][3] = __float_as_uint(hi.y);
            }
#pragma unroll
            for (int nt = 0; nt < 8; nt++) {
                int nr = wn * 64 + nt * 8 + g;
                float2 b = *(const float2*)(Bs + nr * GST + kc);
                mma_tf32(acc[0][nt], a[0], __float_as_uint(b.x), __float_as_uint(b.y));
                mma_tf32(acc[1][nt], a[1], __float_as_uint(b.x), __float_as_uint(b.y));
            }
        }
        __syncthreads();
        if (s + 2 < S) load_stage(s + 2, s & 1);
    }

    // epilogue
#pragma unroll
    for (int mt = 0; mt < 2; mt++)
#pragma unroll
        for (int nt = 0; nt < 8; nt++) {
            int r0 = by * 128 + wm * 32 + mt * 16 + g;
            int c0 = bx * 128 + wn * 64 + nt * 8 + 2 * tc;
            float v0 = acc[mt][nt][0], v1 = acc[mt][nt][1];
            float v2 = acc[mt][nt][2], v3 = acc[mt][nt][3];
            if (MODE == 1) {
                float sc = (c0 < DM) ? 0.125f : 1.0f;
                v0 = f2tff(v0 * sc); v1 = f2tff(v1 * sc);
                v2 = f2tff(v2 * sc); v3 = f2tff(v3 * sc);
            }
            *(float2*)(C + (size_t)r0 * N + c0)       = make_float2(v0, v1);
            *(float2*)(C + (size_t)(r0 + 8) * N + c0) = make_float2(v2, v3);
        }
}

// ---------------------------------------------------------------------------
// Causal flash attention: 64 q-rows, 4 warps, 3 CTA/SM, software-pipelined
// K/V loads (split commit groups: K_{t+1} loads during softmax/P@V of t,
// V_t loads during S of t).
// ---------------------------------------------------------------------------
#define ROWP 68
__global__ __launch_bounds__(128) void attn_fwd()
{
    extern __shared__ float sm[];
    float* Qs = sm;
    float* Ks = Qs + 64 * ROWP;
    float* Vs = Ks + 64 * ROWP;
    float* Ps = Vs + 64 * ROWP;
    const uint32_t sb = s2u(sm);

    const int tid  = threadIdx.x;
    const int lane = tid & 31;
    const int warp = tid >> 5;
    const int h    = blockIdx.y;
    const int qt   = (int)gridDim.x - 1 - (int)blockIdx.x;  // heavy tiles first
    const int q0   = qt * 64;
    const int g    = lane >> 2;
    const int tc   = lane & 3;

    auto load_k = [&](int t) {
#pragma unroll
        for (int i = 0; i < 8; i++) {
            int idx = tid + i * 128;
            int r   = idx >> 4;
            int c4  = (idx & 15) * 4;
            cpa16(sb + (uint32_t)(64 * ROWP + r * ROWP + c4) * 4,
                  g_qkv + (size_t)(t * 64 + r) * (3 * DM) + DM + h * DH + c4);
        }
        cpa_commit();
    };
    auto load_v = [&](int t) {
#pragma unroll
        for (int i = 0; i < 8; i++) {
            int idx = tid + i * 128;
            int r   = idx >> 4;
            int c4  = (idx & 15) * 4;
            cpa16(sb + (uint32_t)(128 * ROWP + r * ROWP + c4) * 4,
                  g_qkv + (size_t)(t * 64 + r) * (3 * DM) + 2 * DM + h * DH + c4);
        }
        cpa_commit();
    };

    // ---- prologue: group1 = Q + K0, group2 = V0 ----
#pragma unroll
    for (int i = 0; i < 8; i++) {
        int idx = tid + i * 128;
        int r   = idx >> 4;
        int c4  = (idx & 15) * 4;
        cpa16(sb + (uint32_t)(r * ROWP + c4) * 4,
              g_qkv + (size_t)(q0 + r) * (3 * DM) + h * DH + c4);
    }
    load_k(0);      // commits Q+K0 together
    load_v(0);

    float o[8][4];
#pragma unroll
    for (int nt = 0; nt < 8; nt++)
#pragma unroll
        for (int j = 0; j < 4; j++) o[nt][j] = 0.f;
    float mA = -INFINITY, mB = -INFINITY, lA = 0.f, lB = 0.f;

    for (int t = 0; t <= qt; t++) {
        // ---- wait K_t (V_t still in flight), make visible to all warps ----
        cpa_wait<1>();
        __syncthreads();

        // ---- S = Q @ K^T : warp computes 16 x 64 ----
        float s[8][4];
#pragma unroll
        for (int nt = 0; nt < 8; nt++)
#pragma unroll
            for (int j = 0; j < 4; j++) s[nt][j] = 0.f;

#pragma unroll
        for (int ks = 0; ks < 8; ks++) {
            unsigned a[4];
            int row = warp * 16 + g;
            int col = ks * 8 + tc;
            a[0] = __float_as_uint(Qs[row * ROWP + col]);
            a[1] = __float_as_uint(Qs[(row + 8) * ROWP + col]);
            a[2] = __float_as_uint(Qs[row * ROWP + col + 4]);
            a[3] = __float_as_uint(Qs[(row + 8) * ROWP + col + 4]);
#pragma unroll
            for (int nt = 0; nt < 8; nt++) {
                int nc = nt * 8 + g;
                unsigned b0 = __float_as_uint(Ks[nc * ROWP + col]);
                unsigned b1 = __float_as_uint(Ks[nc * ROWP + col + 4]);
                mma_tf32(s[nt], a, b0, b1);
            }
        }

        // ---- all warps done with K buffer -> prefetch K_{t+1} ----
        __syncthreads();
        if (t < qt) load_k(t + 1);

        // ---- causal mask on diagonal tile ----
        if (t == qt) {
            int qlA = warp * 16 + g;
            int qlB = qlA + 8;
#pragma unroll
            for (int nt = 0; nt < 8; nt++) {
                int k0 = nt * 8 + 2 * tc;
                if (k0     > qlA) s[nt][0] = -INFINITY;
                if (k0 + 1 > qlA) s[nt][1] = -INFINITY;
                if (k0     > qlB) s[nt][2] = -INFINITY;
                if (k0 + 1 > qlB) s[nt][3] = -INFINITY;
            }
        }

        // ---- online softmax ----
        float rA = -INFINITY, rB = -INFINITY;
#pragma unroll
        for (int nt = 0; nt < 8; nt++) {
            rA = fmaxf(rA, fmaxf(s[nt][0], s[nt][1]));
            rB = fmaxf(rB, fmaxf(s[nt][2], s[nt][3]));
        }
        rA = fmaxf(rA, __shfl_xor_sync(0xffffffffu, rA, 1));
        rA = fmaxf(rA, __shfl_xor_sync(0xffffffffu, rA, 2));
        rB = fmaxf(rB, __shfl_xor_sync(0xffffffffu, rB, 1));
        rB = fmaxf(rB, __shfl_xor_sync(0xffffffffu, rB, 2));

        float mAn = fmaxf(mA, rA), mBn = fmaxf(mB, rB);
        float fA = __expf(mA - mAn), fB = __expf(mB - mBn);

        float sumA = 0.f, sumB = 0.f;
        int rowL = warp * 16 + g;
#pragma unroll
        for (int nt = 0; nt < 8; nt++) {
            float p0 = f2tff(__expf(s[nt][0] - mAn));
            float p1 = f2tff(__expf(s[nt][1] - mAn));
            float p2 = f2tff(__expf(s[nt][2] - mBn));
            float p3 = f2tff(__expf(s[nt][3] - mBn));
            sumA += p0 + p1;
            sumB += p2 + p3;
            int c0 = nt * 8 + 2 * tc;
            Ps[rowL * ROWP + c0]           = p0;
            Ps[rowL * ROWP + c0 + 1]       = p1;
            Ps[(rowL + 8) * ROWP + c0]     = p2;
            Ps[(rowL + 8) * ROWP + c0 + 1] = p3;
        }
        sumA += __shfl_xor_sync(0xffffffffu, sumA, 1);
        sumA += __shfl_xor_sync(0xffffffffu, sumA, 2);
        sumB += __shfl_xor_sync(0xffffffffu, sumB, 1);
        sumB += __shfl_xor_sync(0xffffffffu, sumB, 2);

        lA = lA * fA + sumA;
        lB = lB * fB + sumB;
        mA = mAn; mB = mBn;
#pragma unroll
        for (int nt = 0; nt < 8; nt++) {
            o[nt][0] *= fA; o[nt][1] *= fA;
            o[nt][2] *= fB; o[nt][3] *= fB;
        }
        __syncwarp();   // each warp consumes only its own P rows

        // ---- wait V_t (K_{t+1} may still be in flight) ----
        if (t < qt) cpa_wait<1>(); else cpa_wait<0>();
        __syncthreads();

        // ---- O += P @ V ----
#pragma unroll
        for (int ks = 0; ks < 8; ks++) {
            unsigned a[4];
            int row = warp * 16 + g;
            int col = ks * 8 + tc;
            a[0] = __float_as_uint(Ps[row * ROWP + col]);
            a[1] = __float_as_uint(Ps[(row + 8) * ROWP + col]);
            a[2] = __float_as_uint(Ps[row * ROWP + col + 4]);
            a[3] = __float_as_uint(Ps[(row + 8) * ROWP + col + 4]);
#pragma unroll
            for (int nt = 0; nt < 8; nt++) {
                unsigned b0 = __float_as_uint(Vs[col * ROWP + nt * 8 + g]);
                unsigned b1 = __float_as_uint(Vs[(col + 4) * ROWP + nt * 8 + g]);
                mma_tf32(o[nt], a, b0, b1);
            }
        }

        // ---- all warps done with V buffer -> prefetch V_{t+1} ----
        __syncthreads();
        if (t < qt) load_v(t + 1);
    }

    // ---- epilogue: normalize, round (proj GEMM input), store normal layout ----
    float invA = 1.f / lA, invB = 1.f / lB;
    int rowA = q0 + warp * 16 + g;
#pragma unroll
    for (int nt = 0; nt < 8; nt++) {
        int c = h * DH + nt * 8 + 2 * tc;
        *(float2*)(g_att + (size_t)rowA * DM + c) =
            make_float2(f2tff(o[nt][0] * invA), f2tff(o[nt][1] * invA));
        *(float2*)(g_att + (size_t)(rowA + 8) * DM + c) =
            make_float2(f2tff(o[nt][2] * invB), f2tff(o[nt][3] * invB));
    }
}

// ---------------------------------------------------------------------------
// Launch
// ---------------------------------------------------------------------------
extern "C" void kernel_launch(void* const* d_in, const int* in_sizes, int n_in,
                              void* d_out, int out_size)
{
    const float* x      = (const float*)d_in[0];
    const float* w_qkv  = (const float*)d_in[1];
    const float* w_proj = (const float*)d_in[2];
    float* out          = (float*)d_out;

    float *qkv_p, *att_p, *xr_p, *wqkvT_p, *wprojT_p;
    cudaGetSymbolAddress((void**)&qkv_p,    g_qkv);
    cudaGetSymbolAddress((void**)&att_p,    g_att);
    cudaGetSymbolAddress((void**)&xr_p,     g_xr);
    cudaGetSymbolAddress((void**)&wqkvT_p,  g_wqkvT);
    cudaGetSymbolAddress((void**)&wprojT_p, g_wprojT);

    const int attn_smem = 4 * 64 * ROWP * (int)sizeof(float);   // 69632 -> 3 CTA/SM
    cudaFuncSetAttribute(attn_fwd, cudaFuncAttributeMaxDynamicSharedMemorySize,
                         attn_smem);

    // 0) pre-process: round + k-permute A operand; transpose+round+permute weights
    cvt_perm_k<<<(TQ * DM / 4 + 255) / 256, 256>>>(x, xr_p, TQ * DM);
    wtrans_perm<<<dim3(3 * DM / 32, DM / 32), dim3(32, 8)>>>(w_qkv, wqkvT_p,
                                                             DM, 3 * DM);
    wtrans_perm<<<dim3(DM / 32, DM / 32), dim3(32, 8)>>>(w_proj, wprojT_p,
                                                         DM, DM);

    // 1) QKV projection: [4096,1024] @ [3072,1024]^T (rounds + scales Q)
    gemm_tf32p<1><<<dim3(3 * DM / 128, TQ / 128), 256>>>(
        xr_p, wqkvT_p, qkv_p, TQ, 3 * DM, DM);

    // 2) causal attention (pipelined K/V loads)
    attn_fwd<<<dim3(TQ / 64, NH), 128, attn_smem>>>();

    // 3) permute attention output for the proj GEMM (reuse g_xr)
    cvt_perm_k<<<(TQ * DM / 4 + 255) / 256, 256>>>(att_p, xr_p, TQ * DM);

    // 4) output projection
    gemm_tf32p<0><<<dim3(DM / 128, TQ / 128), 256>>>(
        xr_p, wprojT_p, out, TQ, DM, DM);
}

// round 7
// speedup vs baseline: 2.4734x; 2.2476x over previous
#include <cuda_runtime.h>
#include <cuda_fp16.h>
#include <cstdint>
#include <cmath>

#define TQ   4096
#define DM   1024
#define NH   16
#define DH   64
#define KW   (DM / 2)          // k-dim in fp16x2 words = 512

// Scratch (__device__ globals: allocation-free rule)
__device__ __half    g_qkv[(size_t)TQ * 3 * DM];     // [t][3c] fp16, Q pre-scaled
__device__ uint32_t  g_att[(size_t)TQ * KW];         // attn out, proj-A perm layout
__device__ uint32_t  g_xw[(size_t)TQ * KW];          // x fp16, word-permuted
__device__ uint32_t  g_wqkvT[(size_t)3 * DM * KW];   // w_qkv^T fp16, word-permuted
__device__ uint32_t  g_wprojT[(size_t)DM * KW];      // w_proj^T fp16, word-permuted

// ---------------------------------------------------------------------------
// helpers
// ---------------------------------------------------------------------------
__device__ __forceinline__ uint32_t packh2(float a, float b) {
    __half2 h = __floats2half2_rn(a, b);
    return *reinterpret_cast<uint32_t*>(&h);
}

__device__ __forceinline__ void mma_f16(float* d, const uint32_t* a,
                                        uint32_t b0, uint32_t b1) {
    asm volatile(
        "mma.sync.aligned.m16n8k16.row.col.f32.f16.f16.f32 "
        "{%0,%1,%2,%3}, {%4,%5,%6,%7}, {%8,%9}, {%0,%1,%2,%3};\n"
        : "+f"(d[0]), "+f"(d[1]), "+f"(d[2]), "+f"(d[3])
        : "r"(a[0]), "r"(a[1]), "r"(a[2]), "r"(a[3]), "r"(b0), "r"(b1));
}

__device__ __forceinline__ void ldm_x4(uint32_t* r, uint32_t addr) {
    asm volatile("ldmatrix.sync.aligned.m8n8.x4.shared.b16 {%0,%1,%2,%3}, [%4];"
                 : "=r"(r[0]), "=r"(r[1]), "=r"(r[2]), "=r"(r[3]) : "r"(addr));
}
__device__ __forceinline__ void ldm_x4_t(uint32_t* r, uint32_t addr) {
    asm volatile("ldmatrix.sync.aligned.m8n8.x4.trans.shared.b16 {%0,%1,%2,%3}, [%4];"
                 : "=r"(r[0]), "=r"(r[1]), "=r"(r[2]), "=r"(r[3]) : "r"(addr));
}

__device__ __forceinline__ uint32_t s2u(const void* p) {
    uint32_t a;
    asm("{ .reg .u64 t; cvta.to.shared.u64 t, %1; cvt.u32.u64 %0, t; }"
        : "=r"(a) : "l"(p));
    return a;
}
__device__ __forceinline__ void cpa16(uint32_t dst, const void* src) {
    asm volatile("cp.async.cg.shared.global [%0], [%1], 16;\n" :: "r"(dst), "l"(src));
}
__device__ __forceinline__ void cpa_commit() {
    asm volatile("cp.async.commit_group;\n");
}
template <int N> __device__ __forceinline__ void cpa_wait() {
    asm volatile("cp.async.wait_group %0;\n" :: "n"(N));
}

// ---------------------------------------------------------------------------
// pre-processing: fp32 -> fp16 words, permuted within 8-word (16-elem) groups.
// physical word wp holds logical word ((wp&1)<<2)|(wp>>1); so a thread's words
// (tc, tc+4) sit at physical (2tc, 2tc+1) -> one LDS.64 per fragment pair.
// ---------------------------------------------------------------------------
__global__ void cvt_x_h(const float* __restrict__ in, uint32_t* __restrict__ out,
                        int ngroups)
{
    int gidx = blockIdx.x * blockDim.x + threadIdx.x;
    if (gidx >= ngroups) return;
    const float4* p = (const float4*)(in + (size_t)gidx * 16);
    float f[16];
#pragma unroll
    for (int i = 0; i < 4; i++) {
        float4 v = p[i];
        f[4 * i] = v.x; f[4 * i + 1] = v.y; f[4 * i + 2] = v.z; f[4 * i + 3] = v.w;
    }
    uint32_t w[8];
#pragma unroll
    for (int wp = 0; wp < 8; wp++) {
        int lw = ((wp & 1) << 2) | (wp >> 1);
        w[wp] = packh2(f[2 * lw], f[2 * lw + 1]);
    }
    uint4* o = (uint4*)(out + (size_t)gidx * 8);
    o[0] = make_uint4(w[0], w[1], w[2], w[3]);
    o[1] = make_uint4(w[4], w[5], w[6], w[7]);
}

// in [R][C] fp32 -> out [C][R/2 words] fp16x2, k(=R)-dim word-permuted.
__global__ void wtrans_h(const float* __restrict__ in, uint32_t* __restrict__ out,
                         int R, int C)
{
    __shared__ float t[32][33];
    int c0 = blockIdx.x * 32, r0 = blockIdx.y * 32;
    int tx = threadIdx.x, ty = threadIdx.y;
#pragma unroll
    for (int i = 0; i < 4; i++)
        t[ty + 8 * i][tx] = in[(size_t)(r0 + ty + 8 * i) * C + c0 + tx];
    __syncthreads();
    int Rw = R / 2;
#pragma unroll
    for (int i = 0; i < 2; i++) {
        int wp  = ty + 8 * i;                 // local physical word 0..15
        int p7  = wp & 7;
        int lwl = (wp & ~7) | (((p7 & 1) << 2) | (p7 >> 1));
        int k0  = 2 * lwl;
        out[(size_t)(c0 + tx) * Rw + r0 / 2 + wp] =
            packh2(t[k0][tx], t[k0 + 1][tx]);
    }
}

// ---------------------------------------------------------------------------
// fp16 GEMM on word-permuted operands: C[M,N] = A[M,K] @ B[N,K]^T
// BM=128, BN=128, stage = 32 words (K=64), 256 thr, 2-stage cp.async,
// LDS.64 fragments, mma m16n8k16.
// MODE 1 (qkv): fp16 output, cols < DM (Q) scaled 0.125. MODE 0: fp32 out.
// ---------------------------------------------------------------------------
#define GST 40
#define GSTAGE (2 * 128 * GST)

template <int MODE>
__global__ __launch_bounds__(256, 2)
void gemm_h(const uint32_t* __restrict__ A, const uint32_t* __restrict__ B,
            void* __restrict__ Cv, int M, int N, int Kw)
{
    __shared__ uint32_t sm[2 * GSTAGE];
    const uint32_t s0 = s2u(sm);

    const int tid  = threadIdx.x;
    const int lane = tid & 31;
    const int warp = tid >> 5;
    const int wm   = warp & 3;
    const int wn   = warp >> 2;
    const int bx   = blockIdx.x;
    const int by   = blockIdx.y;
    const int g    = lane >> 2;
    const int tc   = lane & 3;

    const uint32_t* Ab = A + (size_t)(by * 128) * Kw;
    const uint32_t* Bb = B + (size_t)(bx * 128) * Kw;

    float acc[2][8][4];
#pragma unroll
    for (int mt = 0; mt < 2; mt++)
#pragma unroll
        for (int nt = 0; nt < 8; nt++)
#pragma unroll
            for (int j = 0; j < 4; j++) acc[mt][nt][j] = 0.f;

    auto load_stage = [&](int s, int buf) {
        uint32_t dA = s0 + (uint32_t)(buf * GSTAGE) * 4;
        uint32_t dB = dA + (uint32_t)(128 * GST) * 4;
#pragma unroll
        for (int j = 0; j < 4; j++) {
            int idx = tid + j * 256;
            int r = idx >> 3, c4 = (idx & 7) * 4;       // words
            cpa16(dA + (uint32_t)(r * GST + c4) * 4, Ab + (size_t)r * Kw + s * 32 + c4);
            cpa16(dB + (uint32_t)(r * GST + c4) * 4, Bb + (size_t)r * Kw + s * 32 + c4);
        }
        cpa_commit();
    };

    load_stage(0, 0);
    load_stage(1, 1);

    const int S = Kw / 32;
    for (int s = 0; s < S; s++) {
        if (s + 1 < S) cpa_wait<1>(); else cpa_wait<0>();
        __syncthreads();

        const uint32_t* As = sm + (s & 1) * GSTAGE;
        const uint32_t* Bs = As + 128 * GST;

#pragma unroll
        for (int ks = 0; ks < 4; ks++) {
            int kc = ks * 8 + 2 * tc;                   // physical word pair
            uint32_t a[2][4];
#pragma unroll
            for (int mt = 0; mt < 2; mt++) {
                int row = wm * 32 + mt * 16 + g;
                uint2 lo = *(const uint2*)(As + row * GST + kc);
                uint2 hi = *(const uint2*)(As + (row + 8) * GST + kc);
                a[mt][0] = lo.x; a[mt][1] = hi.x; a[mt][2] = lo.y; a[mt][3] = hi.y;
            }
#pragma unroll
            for (int nt = 0; nt < 8; nt++) {
                int nr = wn * 64 + nt * 8 + g;
                uint2 b = *(const uint2*)(Bs + nr * GST + kc);
                mma_f16(acc[0][nt], a[0], b.x, b.y);
                mma_f16(acc[1][nt], a[1], b.x, b.y);
            }
        }
        __syncthreads();
        if (s + 2 < S) load_stage(s + 2, s & 1);
    }

    // epilogue
#pragma unroll
    for (int mt = 0; mt < 2; mt++)
#pragma unroll
        for (int nt = 0; nt < 8; nt++) {
            int r0 = by * 128 + wm * 32 + mt * 16 + g;
            int c0 = bx * 128 + wn * 64 + nt * 8 + 2 * tc;
            float v0 = acc[mt][nt][0], v1 = acc[mt][nt][1];
            float v2 = acc[mt][nt][2], v3 = acc[mt][nt][3];
            if (MODE == 1) {
                float sc = (c0 < DM) ? 0.125f : 1.0f;   // fold q-scale
                uint32_t* C = (uint32_t*)Cv;
                int cw = c0 >> 1;
                C[(size_t)r0 * (N / 2) + cw]       = packh2(v0 * sc, v1 * sc);
                C[(size_t)(r0 + 8) * (N / 2) + cw] = packh2(v2 * sc, v3 * sc);
            } else {
                float* C = (float*)Cv;
                *(float2*)(C + (size_t)r0 * N + c0)       = make_float2(v0, v1);
                *(float2*)(C + (size_t)(r0 + 8) * N + c0) = make_float2(v2, v3);
            }
        }
}

// ---------------------------------------------------------------------------
// Causal flash attention, fp16 mma m16n8k16. 64 q-rows, 4 warps.
// Q/K/V fragments via ldmatrix (V with .trans); P passes S->PV in registers.
// smem 27.6 KB -> ~4 CTA/SM.
// ---------------------------------------------------------------------------
#define RW 36                      // smem row stride in words (64 fp16 + pad)
__global__ __launch_bounds__(128) void attn_fwd()
{
    __shared__ __align__(16) uint32_t smQ[64 * RW];
    __shared__ __align__(16) uint32_t smK[64 * RW];
    __shared__ __align__(16) uint32_t smV[64 * RW];
    const uint32_t bQ = s2u(smQ), bK = s2u(smK), bV = s2u(smV);

    const int tid  = threadIdx.x;
    const int lane = tid & 31;
    const int warp = tid >> 5;
    const int h    = blockIdx.y;
    const int qt   = (int)gridDim.x - 1 - (int)blockIdx.x;  // heavy tiles first
    const int q0   = qt * 64;
    const int g    = lane >> 2;
    const int tc   = lane & 3;

    // ---- prologue: Q tile (64 x 64 fp16 = 512 x 16B) ----
#pragma unroll
    for (int i = 0; i < 4; i++) {
        int idx = tid + i * 128;
        int r = idx >> 3, ch = idx & 7;
        cpa16(bQ + (uint32_t)(r * RW + ch * 4) * 4,
              g_qkv + (size_t)(q0 + r) * (3 * DM) + h * DH + ch * 8);
    }
    cpa_commit();

    // ldmatrix base offsets (per-thread constant parts)
    const uint32_t qoff = (uint32_t)((warp * 16 + (lane & 15)) * RW +
                                     ((lane >> 4) << 2)) * 4;
    const uint32_t koff = (uint32_t)(((lane & 7) + ((lane >> 4) << 3)) * RW +
                                     (((lane >> 3) & 1) << 2)) * 4;
    const uint32_t voff = (uint32_t)((lane & 15) * RW + ((lane >> 4) << 2)) * 4;

    float o[8][4];
#pragma unroll
    for (int nt = 0; nt < 8; nt++)
#pragma unroll
        for (int j = 0; j < 4; j++) o[nt][j] = 0.f;
    float mA = -INFINITY, mB = -INFINITY, lA = 0.f, lB = 0.f;

    for (int t = 0; t <= qt; t++) {
        __syncthreads();           // prior tile's PV done with K/V buffers
#pragma unroll
        for (int i = 0; i < 4; i++) {
            int idx = tid + i * 128;
            int r = idx >> 3, ch = idx & 7;
            const __half* base = g_qkv + (size_t)(t * 64 + r) * (3 * DM) + h * DH + ch * 8;
            cpa16(bK + (uint32_t)(r * RW + ch * 4) * 4, base + DM);
            cpa16(bV + (uint32_t)(r * RW + ch * 4) * 4, base + 2 * DM);
        }
        cpa_commit();
        cpa_wait<0>();
        __syncthreads();

        // ---- S = Q @ K^T : warp computes 16 x 64 ----
        float s[8][4];
#pragma unroll
        for (int nt = 0; nt < 8; nt++)
#pragma unroll
            for (int j = 0; j < 4; j++) s[nt][j] = 0.f;

#pragma unroll
        for (int kc = 0; kc < 4; kc++) {
            uint32_t a[4];
            ldm_x4(a, bQ + qoff + (uint32_t)(8 * kc) * 4);
#pragma unroll
            for (int ntp = 0; ntp < 4; ntp++) {
                uint32_t b[4];
                ldm_x4(b, bK + koff + (uint32_t)(ntp * 16 * RW + 8 * kc) * 4);
                mma_f16(s[2 * ntp],     a, b[0], b[1]);
                mma_f16(s[2 * ntp + 1], a, b[2], b[3]);
            }
        }

        // ---- causal mask on diagonal tile ----
        if (t == qt) {
            int qlA = warp * 16 + g;
            int qlB = qlA + 8;
#pragma unroll
            for (int nt = 0; nt < 8; nt++) {
                int k0 = nt * 8 + 2 * tc;
                if (k0     > qlA) s[nt][0] = -INFINITY;
                if (k0 + 1 > qlA) s[nt][1] = -INFINITY;
                if (k0     > qlB) s[nt][2] = -INFINITY;
                if (k0 + 1 > qlB) s[nt][3] = -INFINITY;
            }
        }

        // ---- online softmax (p kept fp32 in s[][]) ----
        float rA = -INFINITY, rB = -INFINITY;
#pragma unroll
        for (int nt = 0; nt < 8; nt++) {
            rA = fmaxf(rA, fmaxf(s[nt][0], s[nt][1]));
            rB = fmaxf(rB, fmaxf(s[nt][2], s[nt][3]));
        }
        rA = fmaxf(rA, __shfl_xor_sync(0xffffffffu, rA, 1));
        rA = fmaxf(rA, __shfl_xor_sync(0xffffffffu, rA, 2));
        rB = fmaxf(rB, __shfl_xor_sync(0xffffffffu, rB, 1));
        rB = fmaxf(rB, __shfl_xor_sync(0xffffffffu, rB, 2));

        float mAn = fmaxf(mA, rA), mBn = fmaxf(mB, rB);
        float fA = __expf(mA - mAn), fB = __expf(mB - mBn);

        float sumA = 0.f, sumB = 0.f;
#pragma unroll
        for (int nt = 0; nt < 8; nt++) {
            s[nt][0] = __expf(s[nt][0] - mAn);
            s[nt][1] = __expf(s[nt][1] - mAn);
            s[nt][2] = __expf(s[nt][2] - mBn);
            s[nt][3] = __expf(s[nt][3] - mBn);
            sumA += s[nt][0] + s[nt][1];
            sumB += s[nt][2] + s[nt][3];
        }
        sumA += __shfl_xor_sync(0xffffffffu, sumA, 1);
        sumA += __shfl_xor_sync(0xffffffffu, sumA, 2);
        sumB += __shfl_xor_sync(0xffffffffu, sumB, 1);
        sumB += __shfl_xor_sync(0xffffffffu, sumB, 2);

        lA = lA * fA + sumA;
        lB = lB * fB + sumB;
        mA = mAn; mB = mBn;
#pragma unroll
        for (int nt = 0; nt < 8; nt++) {
            o[nt][0] *= fA; o[nt][1] *= fA;
            o[nt][2] *= fB; o[nt][3] *= fB;
        }

        // ---- O += P @ V  (P a-frags straight from registers; V via .trans) ----
#pragma unroll
        for (int kc = 0; kc < 4; kc++) {
            uint32_t pa[4];
            pa[0] = packh2(s[2 * kc][0],     s[2 * kc][1]);
            pa[1] = packh2(s[2 * kc][2],     s[2 * kc][3]);
            pa[2] = packh2(s[2 * kc + 1][0], s[2 * kc + 1][1]);
            pa[3] = packh2(s[2 * kc + 1][2], s[2 * kc + 1][3]);
#pragma unroll
            for (int ntp = 0; ntp < 4; ntp++) {
                uint32_t b[4];
                ldm_x4_t(b, bV + voff + (uint32_t)(16 * kc * RW + ntp * 8) * 4);
                mma_f16(o[2 * ntp],     pa, b[0], b[1]);
                mma_f16(o[2 * ntp + 1], pa, b[2], b[3]);
            }
        }
    }

    // ---- epilogue: normalize, emit proj-A (word-permuted fp16) layout ----
    float invA = 1.f / lA, invB = 1.f / lB;
    int rowA = q0 + warp * 16 + g;
#pragma unroll
    for (int nt = 0; nt < 8; nt++) {
        int hw   = h * 32 + nt * 4 + tc;                         // logical word
        int phys = (hw & ~7) | (2 * (hw & 3) + ((hw & 7) >> 2)); // permuted
        g_att[(size_t)rowA * KW + phys]       = packh2(o[nt][0] * invA, o[nt][1] * invA);
        g_att[(size_t)(rowA + 8) * KW + phys] = packh2(o[nt][2] * invB, o[nt][3] * invB);
    }
}

// ---------------------------------------------------------------------------
// Launch
// ---------------------------------------------------------------------------
extern "C" void kernel_launch(void* const* d_in, const int* in_sizes, int n_in,
                              void* d_out, int out_size)
{
    const float* x      = (const float*)d_in[0];
    const float* w_qkv  = (const float*)d_in[1];
    const float* w_proj = (const float*)d_in[2];
    float* out          = (float*)d_out;

    void *qkv_p, *att_p, *xw_p, *wqkvT_p, *wprojT_p;
    cudaGetSymbolAddress(&qkv_p,    g_qkv);
    cudaGetSymbolAddress(&att_p,    g_att);
    cudaGetSymbolAddress(&xw_p,     g_xw);
    cudaGetSymbolAddress(&wqkvT_p,  g_wqkvT);
    cudaGetSymbolAddress(&wprojT_p, g_wprojT);

    // 0) pre-process: fp16 convert + word-permute operands
    cvt_x_h<<<(TQ * DM / 16 + 255) / 256, 256>>>(x, (uint32_t*)xw_p, TQ * DM / 16);
    wtrans_h<<<dim3(3 * DM / 32, DM / 32), dim3(32, 8)>>>(w_qkv, (uint32_t*)wqkvT_p,
                                                          DM, 3 * DM);
    wtrans_h<<<dim3(DM / 32, DM / 32), dim3(32, 8)>>>(w_proj, (uint32_t*)wprojT_p,
                                                      DM, DM);

    // 1) QKV projection: fp16 out, Q scaled by 1/8
    gemm_h<1><<<dim3(3 * DM / 128, TQ / 128), 256>>>(
        (const uint32_t*)xw_p, (const uint32_t*)wqkvT_p, qkv_p, TQ, 3 * DM, KW);

    // 2) causal attention (epilogue emits proj-A layout)
    attn_fwd<<<dim3(TQ / 64, NH), 128>>>();

    // 3) output projection: fp32 out
    gemm_h<0><<<dim3(DM / 128, TQ / 128), 256>>>(
        (const uint32_t*)att_p, (const uint32_t*)wprojT_p, out, TQ, DM, KW);
}